// round 1
// baseline (speedup 1.0000x reference)
#include <cuda_runtime.h>
#include <cuda_bf16.h>
#include <math.h>

// Problem constants
#define BB   2
#define SS   2048
#define DD   2048
#define HQ   16
#define HKV  4
#define HD   128
#define GQ   (HQ / HKV)          // 4

// ---------------------------------------------------------------------------
// Scratch (device globals; no dynamic allocation allowed)
// ---------------------------------------------------------------------------
__device__ float g_Q[(size_t)BB * SS * HQ * HD];    // [b*S+s][hq*HD+d]
__device__ float g_K[(size_t)BB * SS * HKV * HD];
__device__ float g_V[(size_t)BB * SS * HKV * HD];
__device__ float g_O[(size_t)BB * SS * HQ * HD];    // attention output, pre-Wo

// ---------------------------------------------------------------------------
// fp32 tiled GEMM: C[M,N] = A[M,K] @ B[K,N], all row-major, dims multiple of tile
// 128x128 block tile, 16 K-tile, 256 threads, 8x8 per-thread micro-tile
// ---------------------------------------------------------------------------
#define GBM 128
#define GBN 128
#define GBK 16

__global__ __launch_bounds__(256) void gemm_kernel(
    const float* __restrict__ A, const float* __restrict__ B,
    float* __restrict__ C, int M, int N, int K)
{
    __shared__ float As[GBK][GBM];   // transposed A tile
    __shared__ float Bs[GBK][GBN];

    const int t = threadIdx.x;
    const int block_m = blockIdx.y * GBM;
    const int block_n = blockIdx.x * GBN;
    const int tx = t & 15;
    const int ty = t >> 4;

    // A-tile load mapping: 2 x float4 per thread
    const int arow = t >> 2;
    const int acol = (t & 3) << 2;
    // B-tile load mapping: 2 x float4 per thread
    const int brow = t >> 5;
    const int bcol = (t & 31) << 2;

    float acc[8][8];
    #pragma unroll
    for (int i = 0; i < 8; i++)
        #pragma unroll
        for (int j = 0; j < 8; j++) acc[i][j] = 0.0f;

    for (int k0 = 0; k0 < K; k0 += GBK) {
        #pragma unroll
        for (int u = 0; u < 2; u++) {
            int r = arow + u * 64;
            float4 v = *(const float4*)(A + (size_t)(block_m + r) * K + k0 + acol);
            As[acol + 0][r] = v.x;
            As[acol + 1][r] = v.y;
            As[acol + 2][r] = v.z;
            As[acol + 3][r] = v.w;
        }
        #pragma unroll
        for (int u = 0; u < 2; u++) {
            int r = brow + u * 8;
            *(float4*)&Bs[r][bcol] =
                *(const float4*)(B + (size_t)(k0 + r) * N + block_n + bcol);
        }
        __syncthreads();

        #pragma unroll
        for (int kk = 0; kk < GBK; kk++) {
            float a[8], bv[8];
            *(float4*)&a[0]  = *(const float4*)&As[kk][ty * 8];
            *(float4*)&a[4]  = *(const float4*)&As[kk][ty * 8 + 4];
            *(float4*)&bv[0] = *(const float4*)&Bs[kk][tx * 8];
            *(float4*)&bv[4] = *(const float4*)&Bs[kk][tx * 8 + 4];
            #pragma unroll
            for (int i = 0; i < 8; i++)
                #pragma unroll
                for (int j = 0; j < 8; j++)
                    acc[i][j] += a[i] * bv[j];
        }
        __syncthreads();
    }

    #pragma unroll
    for (int i = 0; i < 8; i++) {
        int r = block_m + ty * 8 + i;
        #pragma unroll
        for (int j = 0; j < 8; j += 4)
            *(float4*)(C + (size_t)r * N + block_n + tx * 8 + j) = *(float4*)&acc[i][j];
    }
}

// ---------------------------------------------------------------------------
// Fused RMSNorm + RoPE (in place), one block per (b*S+s, head) row of 128
// ---------------------------------------------------------------------------
__global__ __launch_bounds__(128) void norm_rope_kernel(
    float* __restrict__ X, const float* __restrict__ w,
    const float* __restrict__ cosT, const float* __restrict__ sinT, int H)
{
    __shared__ float sm[HD];
    __shared__ float red[4];

    const int idx = blockIdx.x;
    const int h   = idx % H;
    const int row = idx / H;       // b*S + s
    const int s   = row % SS;
    float* p = X + (size_t)row * (H * HD) + h * HD;

    const int d = threadIdx.x;
    float v  = p[d];
    float ss = v * v;
    #pragma unroll
    for (int o = 16; o > 0; o >>= 1) ss += __shfl_xor_sync(0xffffffffu, ss, o);
    if ((d & 31) == 0) red[d >> 5] = ss;
    __syncthreads();
    float tot = red[0] + red[1] + red[2] + red[3];
    float r   = rsqrtf(tot * (1.0f / HD) + 1e-8f);
    float xn  = v * r * (1.0f + w[d]);
    sm[d] = xn;
    __syncthreads();
    float rot = (d < HD / 2) ? -sm[d + HD / 2] : sm[d - HD / 2];
    p[d] = xn * cosT[(size_t)s * HD + d] + rot * sinT[(size_t)s * HD + d];
}

// ---------------------------------------------------------------------------
// Sliding-window causal GQA attention (flash-style, fp32)
// grid: (S/TQ, HKV, B), 256 threads.
// Each block: TQ=32 queries x GQ=4 heads = 128 query rows sharing K/V tiles.
// Each thread owns HALF of one query row (64 dims) fully in registers;
// the partner lane (lane^1) owns the other half; dot combined via shfl.
// K/V tiles (TK=64 x 128 fp32 each) in dynamic shared memory.
// ---------------------------------------------------------------------------
#define TQ 32
#define TK 64

__global__ __launch_bounds__(256, 1) void attn_kernel(
    const float* __restrict__ Q, const float* __restrict__ K,
    const float* __restrict__ V, float* __restrict__ O,
    const unsigned char* __restrict__ pad, const int* __restrict__ win_ptr)
{
    extern __shared__ float smem_dyn[];
    float* Ks = smem_dyn;                 // [TK][HD]
    float* Vs = smem_dyn + TK * HD;       // [TK][HD]
    __shared__ unsigned char pads[TK];

    const int qt = blockIdx.x;
    const int n  = blockIdx.y;            // kv head
    const int b  = blockIdx.z;
    const int window = win_ptr[0];

    const int t    = threadIdx.x;
    const int r    = t >> 1;              // query row 0..127
    const int half = t & 1;               // which 64-dim half
    const int gi   = r >> 5;              // group index 0..3
    const int qoff = r & 31;
    const int sq   = qt * TQ + qoff;
    const int hq   = n * GQ + gi;

    const unsigned char padq = pad[(size_t)b * SS + sq];

    // load my half of q into registers
    float4 qv[16];
    {
        const float4* qp = (const float4*)(Q + (((size_t)(b * SS + sq)) * HQ + hq) * HD + half * 64);
        #pragma unroll
        for (int i = 0; i < 16; i++) qv[i] = qp[i];
    }

    float4 o4[16];
    #pragma unroll
    for (int i = 0; i < 16; i++) o4[i] = make_float4(0.f, 0.f, 0.f, 0.f);
    float m = -1e30f;
    float l = 0.0f;

    const float scale = 0.08838834764831845f;   // 128^-0.5

    const int lo = max(0, qt * TQ - window);
    const int hi = qt * TQ + TQ - 1;

    for (int kt0 = lo; kt0 <= hi; kt0 += TK) {
        __syncthreads();
        // cooperative load of K/V tile (256 threads, 8 float4 each per buffer)
        #pragma unroll
        for (int u = 0; u < 8; u++) {
            int lin = u * 256 + t;             // float4 index 0..2047
            int j   = lin >> 5;                // key row in tile
            int c   = (lin & 31) << 2;         // float col
            int kidx = kt0 + j;
            float4 kk4 = make_float4(0.f, 0.f, 0.f, 0.f);
            float4 vv4 = make_float4(0.f, 0.f, 0.f, 0.f);
            if (kidx < SS) {
                size_t off = (((size_t)(b * SS + kidx)) * HKV + n) * HD + c;
                kk4 = *(const float4*)(K + off);
                vv4 = *(const float4*)(V + off);
            }
            *(float4*)&Ks[j * HD + c] = kk4;
            *(float4*)&Vs[j * HD + c] = vv4;
        }
        if (t < TK) {
            int kidx = kt0 + t;
            pads[t] = (kidx < SS) ? pad[(size_t)b * SS + kidx] : (unsigned char)1;
        }
        __syncthreads();

        for (int j = 0; j < TK; j++) {
            const int kidx = kt0 + j;
            // partial dot over my 64 dims (all lanes participate; shfl needs both)
            float s = 0.0f;
            const float4* kr = (const float4*)&Ks[j * HD + half * 64];
            #pragma unroll
            for (int i = 0; i < 16; i++) {
                float4 kk4 = kr[i];
                s += qv[i].x * kk4.x + qv[i].y * kk4.y + qv[i].z * kk4.z + qv[i].w * kk4.w;
            }
            s += __shfl_xor_sync(0xffffffffu, s, 1);
            s *= scale;

            bool valid = (kidx <= sq) && (sq - kidx <= window) && !pads[j] && !padq;
            if (valid) {
                if (s > m) {
                    float c = __expf(m - s);
                    m = s;
                    l *= c;
                    #pragma unroll
                    for (int i = 0; i < 16; i++) {
                        o4[i].x *= c; o4[i].y *= c; o4[i].z *= c; o4[i].w *= c;
                    }
                }
                float p = __expf(s - m);
                l += p;
                const float4* vr = (const float4*)&Vs[j * HD + half * 64];
                #pragma unroll
                for (int i = 0; i < 16; i++) {
                    float4 vv = vr[i];
                    o4[i].x += p * vv.x; o4[i].y += p * vv.y;
                    o4[i].z += p * vv.z; o4[i].w += p * vv.w;
                }
            }
        }
    }

    // epilogue: O[b,s,hq,:] half = o / l   (0/0 -> nan matches all-masked reference)
    float inv = 1.0f / l;
    float4* op = (float4*)(O + (((size_t)(b * SS + sq)) * HQ + hq) * HD + half * 64);
    #pragma unroll
    for (int i = 0; i < 16; i++) {
        float4 v;
        v.x = o4[i].x * inv; v.y = o4[i].y * inv;
        v.z = o4[i].z * inv; v.w = o4[i].w * inv;
        op[i] = v;
    }
}

// ---------------------------------------------------------------------------
// launch
// ---------------------------------------------------------------------------
extern "C" void kernel_launch(void* const* d_in, const int* in_sizes, int n_in,
                              void* d_out, int out_size)
{
    const float* x    = (const float*)d_in[0];
    const float* Wq   = (const float*)d_in[1];
    const float* Wk   = (const float*)d_in[2];
    const float* Wv   = (const float*)d_in[3];
    const float* Wo   = (const float*)d_in[4];
    const float* qnw  = (const float*)d_in[5];
    const float* knw  = (const float*)d_in[6];
    const float* cosT = (const float*)d_in[7];
    const float* sinT = (const float*)d_in[8];
    const unsigned char* pad = (const unsigned char*)d_in[9];
    const int*   win  = (const int*)d_in[10];
    float* out = (float*)d_out;

    float *qbuf, *kbuf, *vbuf, *obuf;
    cudaGetSymbolAddress((void**)&qbuf, g_Q);
    cudaGetSymbolAddress((void**)&kbuf, g_K);
    cudaGetSymbolAddress((void**)&vbuf, g_V);
    cudaGetSymbolAddress((void**)&obuf, g_O);

    const int M = BB * SS;     // 4096

    // QKV projections
    gemm_kernel<<<dim3((HQ * HD) / GBN, M / GBM), 256>>>(x, Wq, qbuf, M, HQ * HD, DD);
    gemm_kernel<<<dim3((HKV * HD) / GBN, M / GBM), 256>>>(x, Wk, kbuf, M, HKV * HD, DD);
    gemm_kernel<<<dim3((HKV * HD) / GBN, M / GBM), 256>>>(x, Wv, vbuf, M, HKV * HD, DD);

    // RMSNorm + RoPE
    norm_rope_kernel<<<M * HQ, 128>>>(qbuf, qnw, cosT, sinT, HQ);
    norm_rope_kernel<<<M * HKV, 128>>>(kbuf, knw, cosT, sinT, HKV);

    // attention
    static const size_t attn_smem = (size_t)2 * TK * HD * sizeof(float); // 64 KB
    cudaFuncSetAttribute(attn_kernel, cudaFuncAttributeMaxDynamicSharedMemorySize,
                         (int)attn_smem);
    attn_kernel<<<dim3(SS / TQ, HKV, BB), 256, attn_smem>>>(qbuf, kbuf, vbuf, obuf, pad, win);

    // output projection
    gemm_kernel<<<dim3(DD / GBN, M / GBM), 256>>>(obuf, Wo, out, M, DD, DD);
}

// round 7
// speedup vs baseline: 1.1612x; 1.1612x over previous
#include <cuda_runtime.h>
#include <cuda_bf16.h>
#include <math.h>

// Problem constants
#define BB   2
#define SS   2048
#define DD   2048
#define HQ   16
#define HKV  4
#define HD   128
#define GQ   (HQ / HKV)          // 4

// ---------------------------------------------------------------------------
// Scratch (device globals; no dynamic allocation allowed)
// ---------------------------------------------------------------------------
__device__ float g_Q[(size_t)BB * SS * HQ * HD];
__device__ float g_K[(size_t)BB * SS * HKV * HD];
__device__ float g_V[(size_t)BB * SS * HKV * HD];
__device__ float g_O[(size_t)BB * SS * HQ * HD];

// ---------------------------------------------------------------------------
// TF32 split-precision GEMM core: 3-pass tf32 split (hi*hi + hi*lo + lo*hi).
// 128x128 block tile, BK=16, 256 threads (8 warps, 4x2), warp tile 32x64.
// ---------------------------------------------------------------------------
#define GBM 128
#define GBN 128
#define GBK 16
#define AST 136   // smem stride (128 + 8 pad): k*136 === k*8 (mod 32) banks

__device__ __forceinline__ unsigned f2tf32(float f) {
    unsigned u;
    asm("cvt.rna.tf32.f32 %0, %1;" : "=r"(u) : "f"(f));
    return u;
}

__device__ __forceinline__ void mma_tf32(float* c, const unsigned* a, const unsigned* b) {
    asm volatile(
        "mma.sync.aligned.m16n8k8.row.col.f32.tf32.tf32.f32 "
        "{%0,%1,%2,%3}, {%4,%5,%6,%7}, {%8,%9}, {%0,%1,%2,%3};\n"
        : "+f"(c[0]), "+f"(c[1]), "+f"(c[2]), "+f"(c[3])
        : "r"(a[0]), "r"(a[1]), "r"(a[2]), "r"(a[3]), "r"(b[0]), "r"(b[1]));
}

// Shared device body: computes one 128x128 tile of C = A @ B.
// A: [M x K] row-major (K = DD), B: [K x Nout] row-major, C: [M x Nout].
__device__ __forceinline__ void gemm_tile_body(
    const float* __restrict__ A, const float* __restrict__ B,
    float* __restrict__ C, int K, int Nout, int block_m, int block_n)
{
    __shared__ float As_hi[GBK * AST];
    __shared__ float As_lo[GBK * AST];
    __shared__ float Bs_hi[GBK * AST];
    __shared__ float Bs_lo[GBK * AST];

    const int t    = threadIdx.x;
    const int lane = t & 31;
    const int wid  = t >> 5;
    const int warp_m = (wid & 3) * 32;
    const int warp_n = (wid >> 2) * 64;

    // global load mappings
    const int ar = t >> 2;            // A row 0..63 (+64)
    const int ac = (t & 3) << 2;      // A col (k) 0,4,8,12
    const int br = t >> 5;            // B row (k) 0..7 (+8)
    const int bc = (t & 31) << 2;     // B col 0..124

    float acc[2][8][4];
    #pragma unroll
    for (int mt = 0; mt < 2; mt++)
        #pragma unroll
        for (int nt = 0; nt < 8; nt++)
            #pragma unroll
            for (int i = 0; i < 4; i++) acc[mt][nt][i] = 0.0f;

    const int lk = lane & 3;          // frag k sub-index
    const int lg = lane >> 2;         // frag group (0..7)

    for (int k0 = 0; k0 < K; k0 += GBK) {
        // --- stage A tile (128x16), split hi/lo, store transposed [k][m] ---
        #pragma unroll
        for (int u = 0; u < 2; u++) {
            int r = ar + u * 64;
            float4 v = *(const float4*)(A + (size_t)(block_m + r) * K + k0 + ac);
            float f[4] = {v.x, v.y, v.z, v.w};
            #pragma unroll
            for (int j = 0; j < 4; j++) {
                unsigned hi = f2tf32(f[j]);
                float lo = f[j] - __uint_as_float(hi);
                As_hi[(ac + j) * AST + r] = __uint_as_float(hi);
                As_lo[(ac + j) * AST + r] = __uint_as_float(f2tf32(lo));
            }
        }
        // --- stage B tile (16x128), split hi/lo, row-major [k][n] ---
        #pragma unroll
        for (int u = 0; u < 2; u++) {
            int r = br + u * 8;
            float4 v = *(const float4*)(B + (size_t)(k0 + r) * Nout + block_n + bc);
            float f[4] = {v.x, v.y, v.z, v.w};
            float4 h4, l4;
            float* hp = &h4.x; float* lp = &l4.x;
            #pragma unroll
            for (int j = 0; j < 4; j++) {
                unsigned hi = f2tf32(f[j]);
                float lo = f[j] - __uint_as_float(hi);
                hp[j] = __uint_as_float(hi);
                lp[j] = __uint_as_float(f2tf32(lo));
            }
            *(float4*)&Bs_hi[r * AST + bc] = h4;
            *(float4*)&Bs_lo[r * AST + bc] = l4;
        }
        __syncthreads();

        #pragma unroll
        for (int ks = 0; ks < GBK; ks += 8) {
            unsigned afr[2][4];
            unsigned bfr[8][2];

            // A-hi frags
            #pragma unroll
            for (int mt = 0; mt < 2; mt++) {
                int m0 = warp_m + mt * 16 + lg;
                afr[mt][0] = __float_as_uint(As_hi[(ks + lk) * AST + m0]);
                afr[mt][1] = __float_as_uint(As_hi[(ks + lk) * AST + m0 + 8]);
                afr[mt][2] = __float_as_uint(As_hi[(ks + lk + 4) * AST + m0]);
                afr[mt][3] = __float_as_uint(As_hi[(ks + lk + 4) * AST + m0 + 8]);
            }
            // B-lo frags ; mma (Ahi, Blo)
            #pragma unroll
            for (int nt = 0; nt < 8; nt++) {
                int n0 = warp_n + nt * 8 + lg;
                bfr[nt][0] = __float_as_uint(Bs_lo[(ks + lk) * AST + n0]);
                bfr[nt][1] = __float_as_uint(Bs_lo[(ks + lk + 4) * AST + n0]);
            }
            #pragma unroll
            for (int nt = 0; nt < 8; nt++)
                #pragma unroll
                for (int mt = 0; mt < 2; mt++)
                    mma_tf32(acc[mt][nt], afr[mt], bfr[nt]);

            // B-hi frags ; mma (Ahi, Bhi)
            #pragma unroll
            for (int nt = 0; nt < 8; nt++) {
                int n0 = warp_n + nt * 8 + lg;
                bfr[nt][0] = __float_as_uint(Bs_hi[(ks + lk) * AST + n0]);
                bfr[nt][1] = __float_as_uint(Bs_hi[(ks + lk + 4) * AST + n0]);
            }
            #pragma unroll
            for (int nt = 0; nt < 8; nt++)
                #pragma unroll
                for (int mt = 0; mt < 2; mt++)
                    mma_tf32(acc[mt][nt], afr[mt], bfr[nt]);

            // A-lo frags ; mma (Alo, Bhi)
            #pragma unroll
            for (int mt = 0; mt < 2; mt++) {
                int m0 = warp_m + mt * 16 + lg;
                afr[mt][0] = __float_as_uint(As_lo[(ks + lk) * AST + m0]);
                afr[mt][1] = __float_as_uint(As_lo[(ks + lk) * AST + m0 + 8]);
                afr[mt][2] = __float_as_uint(As_lo[(ks + lk + 4) * AST + m0]);
                afr[mt][3] = __float_as_uint(As_lo[(ks + lk + 4) * AST + m0 + 8]);
            }
            #pragma unroll
            for (int nt = 0; nt < 8; nt++)
                #pragma unroll
                for (int mt = 0; mt < 2; mt++)
                    mma_tf32(acc[mt][nt], afr[mt], bfr[nt]);
        }
        __syncthreads();
    }

    // epilogue
    #pragma unroll
    for (int mt = 0; mt < 2; mt++) {
        #pragma unroll
        for (int nt = 0; nt < 8; nt++) {
            int r0 = block_m + warp_m + mt * 16 + lg;
            int c0 = block_n + warp_n + nt * 8 + lk * 2;
            *(float2*)(C + (size_t)r0 * Nout + c0)       = make_float2(acc[mt][nt][0], acc[mt][nt][1]);
            *(float2*)(C + (size_t)(r0 + 8) * Nout + c0) = make_float2(acc[mt][nt][2], acc[mt][nt][3]);
        }
    }
}

// Plain GEMM (used for the output projection)
__global__ __launch_bounds__(256, 2) void gemm_tf32_kernel(
    const float* __restrict__ A, const float* __restrict__ B,
    float* __restrict__ C, int M, int N, int K)
{
    gemm_tile_body(A, B, C, K, N, blockIdx.y * GBM, blockIdx.x * GBN);
}

// Fused QKV projection: one launch, N-tiles routed to (Wq,gQ)/(Wk,gK)/(Wv,gV).
// grid.x = 24 N-tiles: [0,16) -> Q (N=2048), [16,20) -> K (N=512), [20,24) -> V.
__global__ __launch_bounds__(256, 2) void gemm_qkv_kernel(
    const float* __restrict__ x,
    const float* __restrict__ Wq, const float* __restrict__ Wk,
    const float* __restrict__ Wv,
    float* __restrict__ Qo, float* __restrict__ Ko, float* __restrict__ Vo)
{
    const int nt = blockIdx.x;
    const float* Bp;
    float* Cp;
    int Nout, tile;
    if (nt < 16)      { Bp = Wq; Cp = Qo; Nout = HQ * HD;  tile = nt; }
    else if (nt < 20) { Bp = Wk; Cp = Ko; Nout = HKV * HD; tile = nt - 16; }
    else              { Bp = Wv; Cp = Vo; Nout = HKV * HD; tile = nt - 20; }
    gemm_tile_body(x, Bp, Cp, DD, Nout, blockIdx.y * GBM, tile * GBN);
}

// ---------------------------------------------------------------------------
// Fused RMSNorm + RoPE (in place), one block per (b*S+s, head) row of 128
// ---------------------------------------------------------------------------
__global__ __launch_bounds__(128) void norm_rope_kernel(
    float* __restrict__ X, const float* __restrict__ w,
    const float* __restrict__ cosT, const float* __restrict__ sinT, int H)
{
    __shared__ float sm[HD];
    __shared__ float red[4];

    const int idx = blockIdx.x;
    const int h   = idx % H;
    const int row = idx / H;       // b*S + s
    const int s   = row % SS;
    float* p = X + (size_t)row * (H * HD) + h * HD;

    const int d = threadIdx.x;
    float v  = p[d];
    float ss = v * v;
    #pragma unroll
    for (int o = 16; o > 0; o >>= 1) ss += __shfl_xor_sync(0xffffffffu, ss, o);
    if ((d & 31) == 0) red[d >> 5] = ss;
    __syncthreads();
    float tot = red[0] + red[1] + red[2] + red[3];
    float r   = rsqrtf(tot * (1.0f / HD) + 1e-8f);
    float xn  = v * r * (1.0f + w[d]);
    sm[d] = xn;
    __syncthreads();
    float rot = (d < HD / 2) ? -sm[d + HD / 2] : sm[d - HD / 2];
    p[d] = xn * cosT[(size_t)s * HD + d] + rot * sinT[(size_t)s * HD + d];
}

// ---------------------------------------------------------------------------
// Sliding-window causal GQA attention (flash-style, fp32)
// ---------------------------------------------------------------------------
#define TQ 32
#define TK 64

__global__ __launch_bounds__(256, 1) void attn_kernel(
    const float* __restrict__ Q, const float* __restrict__ K,
    const float* __restrict__ V, float* __restrict__ O,
    const unsigned char* __restrict__ pad, const int* __restrict__ win_ptr)
{
    extern __shared__ float smem_dyn[];
    float* Ks = smem_dyn;                 // [TK][HD]
    float* Vs = smem_dyn + TK * HD;       // [TK][HD]
    __shared__ unsigned char pads[TK];

    const int qt = blockIdx.x;
    const int n  = blockIdx.y;            // kv head
    const int b  = blockIdx.z;
    const int window = win_ptr[0];

    const int t    = threadIdx.x;
    const int r    = t >> 1;              // query row 0..127
    const int half = t & 1;               // which 64-dim half
    const int gi   = r >> 5;              // group index 0..3
    const int qoff = r & 31;
    const int sq   = qt * TQ + qoff;
    const int hq   = n * GQ + gi;

    const unsigned char padq = pad[(size_t)b * SS + sq];

    float4 qv[16];
    {
        const float4* qp = (const float4*)(Q + (((size_t)(b * SS + sq)) * HQ + hq) * HD + half * 64);
        #pragma unroll
        for (int i = 0; i < 16; i++) qv[i] = qp[i];
    }

    float4 o4[16];
    #pragma unroll
    for (int i = 0; i < 16; i++) o4[i] = make_float4(0.f, 0.f, 0.f, 0.f);
    float m = -1e30f;
    float l = 0.0f;

    const float scale = 0.08838834764831845f;   // 128^-0.5

    const int lo = max(0, qt * TQ - window);
    const int hi = qt * TQ + TQ - 1;

    for (int kt0 = lo; kt0 <= hi; kt0 += TK) {
        __syncthreads();
        #pragma unroll
        for (int u = 0; u < 8; u++) {
            int lin = u * 256 + t;
            int j   = lin >> 5;
            int c   = (lin & 31) << 2;
            int kidx = kt0 + j;
            float4 kk4 = make_float4(0.f, 0.f, 0.f, 0.f);
            float4 vv4 = make_float4(0.f, 0.f, 0.f, 0.f);
            if (kidx < SS) {
                size_t off = (((size_t)(b * SS + kidx)) * HKV + n) * HD + c;
                kk4 = *(const float4*)(K + off);
                vv4 = *(const float4*)(V + off);
            }
            *(float4*)&Ks[j * HD + c] = kk4;
            *(float4*)&Vs[j * HD + c] = vv4;
        }
        if (t < TK) {
            int kidx = kt0 + t;
            pads[t] = (kidx < SS) ? pad[(size_t)b * SS + kidx] : (unsigned char)1;
        }
        __syncthreads();

        for (int j = 0; j < TK; j++) {
            const int kidx = kt0 + j;
            float s = 0.0f;
            const float4* kr = (const float4*)&Ks[j * HD + half * 64];
            #pragma unroll
            for (int i = 0; i < 16; i++) {
                float4 kk4 = kr[i];
                s += qv[i].x * kk4.x + qv[i].y * kk4.y + qv[i].z * kk4.z + qv[i].w * kk4.w;
            }
            s += __shfl_xor_sync(0xffffffffu, s, 1);
            s *= scale;

            bool valid = (kidx <= sq) && (sq - kidx <= window) && !pads[j] && !padq;
            if (valid) {
                if (s > m) {
                    float c = __expf(m - s);
                    m = s;
                    l *= c;
                    #pragma unroll
                    for (int i = 0; i < 16; i++) {
                        o4[i].x *= c; o4[i].y *= c; o4[i].z *= c; o4[i].w *= c;
                    }
                }
                float p = __expf(s - m);
                l += p;
                const float4* vr = (const float4*)&Vs[j * HD + half * 64];
                #pragma unroll
                for (int i = 0; i < 16; i++) {
                    float4 vv = vr[i];
                    o4[i].x += p * vv.x; o4[i].y += p * vv.y;
                    o4[i].z += p * vv.z; o4[i].w += p * vv.w;
                }
            }
        }
    }

    float inv = 1.0f / l;
    float4* op = (float4*)(O + (((size_t)(b * SS + sq)) * HQ + hq) * HD + half * 64);
    #pragma unroll
    for (int i = 0; i < 16; i++) {
        float4 v;
        v.x = o4[i].x * inv; v.y = o4[i].y * inv;
        v.z = o4[i].z * inv; v.w = o4[i].w * inv;
        op[i] = v;
    }
}

// ---------------------------------------------------------------------------
// launch
// ---------------------------------------------------------------------------
extern "C" void kernel_launch(void* const* d_in, const int* in_sizes, int n_in,
                              void* d_out, int out_size)
{
    const float* x    = (const float*)d_in[0];
    const float* Wq   = (const float*)d_in[1];
    const float* Wk   = (const float*)d_in[2];
    const float* Wv   = (const float*)d_in[3];
    const float* Wo   = (const float*)d_in[4];
    const float* qnw  = (const float*)d_in[5];
    const float* knw  = (const float*)d_in[6];
    const float* cosT = (const float*)d_in[7];
    const float* sinT = (const float*)d_in[8];
    const unsigned char* pad = (const unsigned char*)d_in[9];
    const int*   win  = (const int*)d_in[10];
    float* out = (float*)d_out;

    float *qbuf, *kbuf, *vbuf, *obuf;
    cudaGetSymbolAddress((void**)&qbuf, g_Q);
    cudaGetSymbolAddress((void**)&kbuf, g_K);
    cudaGetSymbolAddress((void**)&vbuf, g_V);
    cudaGetSymbolAddress((void**)&obuf, g_O);

    const int M = BB * SS;     // 4096

    // Fused QKV projections (tf32 split tensor-core GEMM, one launch)
    gemm_qkv_kernel<<<dim3(24, M / GBM), 256>>>(x, Wq, Wk, Wv, qbuf, kbuf, vbuf);

    // RMSNorm + RoPE
    norm_rope_kernel<<<M * HQ, 128>>>(qbuf, qnw, cosT, sinT, HQ);
    norm_rope_kernel<<<M * HKV, 128>>>(kbuf, knw, cosT, sinT, HKV);

    // attention
    static const size_t attn_smem = (size_t)2 * TK * HD * sizeof(float); // 64 KB
    cudaFuncSetAttribute(attn_kernel, cudaFuncAttributeMaxDynamicSharedMemorySize,
                         (int)attn_smem);
    attn_kernel<<<dim3(SS / TQ, HKV, BB), 256, attn_smem>>>(qbuf, kbuf, vbuf, obuf, pad, win);

    // output projection
    gemm_tf32_kernel<<<dim3(DD / GBN, M / GBM), 256>>>(obuf, Wo, out, M, DD, DD);
}